// round 5
// baseline (speedup 1.0000x reference)
#include <cuda_runtime.h>

#define A_N 16384
#define R_N 8192
#define DIM 128
#define NB  32

// Scratch (allocation-free rule: __device__ globals). 16 MB total.
__device__ __align__(256) float g_Q[A_N * DIM];
__device__ __align__(256) float g_K[R_N * DIM];
__device__ __align__(256) float g_V[R_N * DIM];
__device__ int g_rseg[NB + 1];

// ---------------------------------------------------------------------------
// GEMM: Out[m][n] = sum_k X[m][k] * W[n][k]   (X @ W^T), N=K=128 fixed.
// Block: 256 threads, tile 64 rows x 128 cols. Warp w owns rows w*8..w*8+7,
// lane owns cols lane*4..lane*4+3 (float4 accumulators).
// ---------------------------------------------------------------------------
__global__ __launch_bounds__(256) void gemm_nt_kernel(
    const float* __restrict__ X, const float* __restrict__ W, int outsel)
{
    __shared__ __align__(16) float Ws[32][132];  // Ws[kk][n] = W[n][kc+kk], padded
    __shared__ __align__(16) float Xs[64][32];   // Xs[row][kk]

    float* Out = (outsel == 0) ? g_Q : (outsel == 1) ? g_K : g_V;

    int t = threadIdx.x;
    int lane = t & 31;
    int w = t >> 5;
    int row0 = blockIdx.x * 64;

    float4 acc[8];
#pragma unroll
    for (int i = 0; i < 8; i++) acc[i] = make_float4(0.f, 0.f, 0.f, 0.f);

    for (int kc = 0; kc < 128; kc += 32) {
        // Stage W chunk (32 k x 128 n): coalesced global reads.
#pragma unroll
        for (int j = 0; j < 16; j++) {
            int idx = t + j * 256;          // 0..4095
            int n = idx >> 5, kk = idx & 31;
            Ws[kk][n] = W[n * 128 + kc + kk];
        }
        // Stage X chunk (64 rows x 32 k).
#pragma unroll
        for (int j = 0; j < 8; j++) {
            int idx = t + j * 256;          // 0..2047
            int row = idx >> 5, kk = idx & 31;
            Xs[row][kk] = X[(row0 + row) * 128 + kc + kk];
        }
        __syncthreads();

#pragma unroll 8
        for (int kk = 0; kk < 32; kk++) {
            float4 w4 = *(const float4*)&Ws[kk][lane * 4];
#pragma unroll
            for (int i = 0; i < 8; i++) {
                float x = Xs[w * 8 + i][kk];   // warp-broadcast
                acc[i].x += x * w4.x;
                acc[i].y += x * w4.y;
                acc[i].z += x * w4.z;
                acc[i].w += x * w4.w;
            }
        }
        __syncthreads();
    }

#pragma unroll
    for (int i = 0; i < 8; i++)
        *(float4*)&Out[(row0 + w * 8 + i) * 128 + lane * 4] = acc[i];
}

// ---------------------------------------------------------------------------
// Residue segment boundaries: g_rseg[b] = first index with residue_batch >= b.
// Batch b's residues = [g_rseg[b], g_rseg[b+1]).
// ---------------------------------------------------------------------------
__global__ void seg_kernel(const int* __restrict__ rb)
{
    int b = threadIdx.x;
    if (b <= NB) {
        int lo = 0, hi = R_N;
        while (lo < hi) {
            int mid = (lo + hi) >> 1;
            if (rb[mid] < b) lo = mid + 1; else hi = mid;
        }
        g_rseg[b] = lo;
    }
}

// ---------------------------------------------------------------------------
// Attention: 64 atoms per block, 256 threads, 32-residue K/V tiles,
// online softmax. Warp w owns atoms w*8 .. w*8+7.
//   scores:  lane = residue index (0..31) within tile
//   PV/out:  lane = dim quad (d = lane*4 .. lane*4+3)
// ---------------------------------------------------------------------------
__global__ __launch_bounds__(256, 2) void attn_kernel(
    const float* __restrict__ atom_h,
    const int* __restrict__ atom_batch,
    const int* __restrict__ residue_batch,
    float* __restrict__ out)
{
    extern __shared__ float sm[];
    float* Qs = sm;                     // 64*128
    float* Ks = Qs + 64 * 128;          // 32*132 (padded rows)
    float* Vs = Ks + 32 * 132;          // 32*128
    float* Ps = Vs + 32 * 128;          // 64*32
    int*   ab  = (int*)(Ps + 64 * 32);  // 64
    int*   rbs = ab + 64;               // 32

    int t = threadIdx.x;
    int lane = t & 31;
    int w = t >> 5;
    int a0 = blockIdx.x * 64;

    // Load Q tile (linear float4 copy).
    {
        const float4* src = (const float4*)(g_Q + a0 * 128);
        float4* dst = (float4*)Qs;
#pragma unroll
        for (int j = 0; j < 8; j++) dst[t + j * 256] = src[t + j * 256];
    }
    if (t < 64) ab[t] = atom_batch[a0 + t];
    __syncthreads();

    // Sorted batches => the block's residue union is one contiguous interval.
    int b_lo = ab[0], b_hi = ab[63];
    int r0 = g_rseg[b_lo];
    int r1 = g_rseg[b_hi + 1];

    float4 acc[8];
    float mcur[8], lsum[8];
    int myb[8];
#pragma unroll
    for (int i = 0; i < 8; i++) {
        acc[i] = make_float4(0.f, 0.f, 0.f, 0.f);
        mcur[i] = -1e30f;
        lsum[i] = 0.f;
        myb[i] = ab[w * 8 + i];
    }
    const float inv_scale = 0.08838834764831845f;  // 1/sqrt(128)
    int d0 = lane * 4;

    for (int rt = r0; rt < r1; rt += 32) {
        int nr = r1 - rt; if (nr > 32) nr = 32;

        // Stage K (stride 132) and V (stride 128) tiles; zero-fill tail.
#pragma unroll
        for (int j = 0; j < 4; j++) {
            int idx = t + j * 256;          // 0..1023 float4 slots
            int r = idx >> 5, c4 = idx & 31;
            float4 kv, vv;
            if (r < nr) {
                kv = ((const float4*)(g_K + (rt + r) * 128))[c4];
                vv = ((const float4*)(g_V + (rt + r) * 128))[c4];
            } else {
                kv = make_float4(0.f, 0.f, 0.f, 0.f);
                vv = kv;
            }
            *(float4*)&Ks[r * 132 + c4 * 4] = kv;
            *(float4*)&Vs[r * 128 + c4 * 4] = vv;
        }
        if (t < 32) rbs[t] = (t < nr) ? residue_batch[rt + t] : -1;
        __syncthreads();

        // Scores: s[i] = Q[a_i] . K[lane]  (float4-vectorized).
        float s[8];
#pragma unroll
        for (int i = 0; i < 8; i++) s[i] = 0.f;
#pragma unroll 8
        for (int k0 = 0; k0 < 128; k0 += 4) {
            float4 k4 = *(const float4*)&Ks[lane * 132 + k0];
#pragma unroll
            for (int i = 0; i < 8; i++) {
                float4 q4 = *(const float4*)&Qs[(w * 8 + i) * 128 + k0];
                s[i] += q4.x * k4.x + q4.y * k4.y + q4.z * k4.z + q4.w * k4.w;
            }
        }

        // Online softmax per atom; one warp owns all 32 residue scores of a row.
        int rbv = rbs[lane];
#pragma unroll
        for (int i = 0; i < 8; i++) {
            float sv = (myb[i] == rbv) ? s[i] * inv_scale : -1e30f;
            float tm = sv;
#pragma unroll
            for (int o = 16; o > 0; o >>= 1)
                tm = fmaxf(tm, __shfl_xor_sync(0xffffffffu, tm, o));
            float mnew = fmaxf(mcur[i], tm);
            float p = (sv > -1e29f) ? __expf(sv - mnew) : 0.f;
            float ps = p;
#pragma unroll
            for (int o = 16; o > 0; o >>= 1)
                ps += __shfl_xor_sync(0xffffffffu, ps, o);
            float factor = __expf(mcur[i] - mnew);   // =1 while row still empty (l=0)
            lsum[i] = lsum[i] * factor + ps;
            mcur[i] = mnew;
            acc[i].x *= factor; acc[i].y *= factor;
            acc[i].z *= factor; acc[i].w *= factor;
            Ps[(w * 8 + i) * 32 + lane] = p;
        }
        __syncwarp();   // producer == consumer warp for Ps rows

        // PV accumulate: lane owns dims d0..d0+3.
#pragma unroll 8
        for (int r = 0; r < 32; r++) {
            float4 v4 = *(const float4*)&Vs[r * 128 + d0];
#pragma unroll
            for (int i = 0; i < 8; i++) {
                float p = Ps[(w * 8 + i) * 32 + r];
                acc[i].x += p * v4.x;
                acc[i].y += p * v4.y;
                acc[i].z += p * v4.z;
                acc[i].w += p * v4.w;
            }
        }
        __syncthreads();
    }

    // Epilogue: out = atom_h + ctx (unchanged if the atom's graph had no residues).
#pragma unroll
    for (int i = 0; i < 8; i++) {
        int a = a0 + w * 8 + i;
        float4 h = ((const float4*)(atom_h + a * 128))[lane];
        float invl = (lsum[i] > 0.f) ? 1.f / lsum[i] : 0.f;
        float4 o;
        o.x = h.x + acc[i].x * invl;
        o.y = h.y + acc[i].y * invl;
        o.z = h.z + acc[i].z * invl;
        o.w = h.w + acc[i].w * invl;
        ((float4*)(out + a * 128))[lane] = o;
    }
}

// ---------------------------------------------------------------------------
extern "C" void kernel_launch(void* const* d_in, const int* in_sizes, int n_in,
                              void* d_out, int out_size)
{
    const float* atom_h        = (const float*)d_in[0];
    const float* residue_h     = (const float*)d_in[1];
    const int*   atom_batch    = (const int*)d_in[2];
    const int*   residue_batch = (const int*)d_in[3];
    const float* W_q           = (const float*)d_in[4];
    const float* W_k           = (const float*)d_in[5];
    const float* W_v           = (const float*)d_in[6];
    float* out = (float*)d_out;

    gemm_nt_kernel<<<A_N / 64, 256>>>(atom_h, W_q, 0);     // Q
    gemm_nt_kernel<<<R_N / 64, 256>>>(residue_h, W_k, 1);  // K
    gemm_nt_kernel<<<R_N / 64, 256>>>(residue_h, W_v, 2);  // V
    seg_kernel<<<1, 64>>>(residue_batch);

    const int SMEM = (64 * 128 + 32 * 132 + 32 * 128 + 64 * 32) * 4 + (64 + 32) * 4;
    cudaFuncSetAttribute(attn_kernel,
                         cudaFuncAttributeMaxDynamicSharedMemorySize, SMEM);
    attn_kernel<<<A_N / 64, 256, SMEM>>>(atom_h, atom_batch, residue_batch, out);
}

// round 6
// speedup vs baseline: 1.0840x; 1.0840x over previous
#include <cuda_runtime.h>

#define A_N 16384
#define R_N 8192
#define DIM 128
#define NB  32

// Scratch (allocation-free rule: __device__ globals). 16 MB total.
__device__ __align__(256) float g_Q[A_N * DIM];
__device__ __align__(256) float g_K[R_N * DIM];
__device__ __align__(256) float g_V[R_N * DIM];
__device__ int g_rseg[NB + 1];

typedef unsigned long long u64;

// Packed fp32x2 helpers (Blackwell FFMA2 path; ptxas never auto-fuses these).
__device__ __forceinline__ void ffma2(u64& d, u64 a, u64 b) {
    asm("fma.rn.f32x2 %0, %1, %2, %0;" : "+l"(d) : "l"(a), "l"(b));
}
__device__ __forceinline__ void fmul2(u64& d, u64 a, u64 b) {
    asm("mul.rn.f32x2 %0, %1, %2;" : "=l"(d) : "l"(a), "l"(b));
}
__device__ __forceinline__ u64 pack2(float lo, float hi) {
    u64 d;
    asm("mov.b64 %0, {%1, %2};" : "=l"(d)
        : "r"(__float_as_uint(lo)), "r"(__float_as_uint(hi)));
    return d;
}
__device__ __forceinline__ void unpack2(float& lo, float& hi, u64 v) {
    unsigned int a, b;
    asm("mov.b64 {%0, %1}, %2;" : "=r"(a), "=r"(b) : "l"(v));
    lo = __uint_as_float(a); hi = __uint_as_float(b);
}

// ---------------------------------------------------------------------------
// GEMM: Out[m][n] = sum_k X[m][k] * W[n][k]   (X @ W^T), N=K=128 fixed.
// 256 threads, 64-row x 128-col tile; warp w owns rows w*8..w*8+7, lane owns
// cols lane*4..lane*4+3 (two packed f32x2 accumulators).
// outsel==0 additionally computes g_rseg in block 0 (replaces seg_kernel).
// ---------------------------------------------------------------------------
__global__ __launch_bounds__(256) void gemm_nt_kernel(
    const float* __restrict__ X, const float* __restrict__ W, int outsel,
    const int* __restrict__ rb)
{
    __shared__ __align__(16) float Ws[32][132];  // Ws[kk][n] = W[n][kc+kk], padded
    __shared__ __align__(16) float Xs[64][32];   // Xs[row][kk]

    float* Out = (outsel == 0) ? g_Q : (outsel == 1) ? g_K : g_V;

    int t = threadIdx.x;
    int lane = t & 31;
    int w = t >> 5;
    int row0 = blockIdx.x * 64;

    u64 acc[8][2];
#pragma unroll
    for (int i = 0; i < 8; i++) { acc[i][0] = 0ull; acc[i][1] = 0ull; }

    for (int kc = 0; kc < 128; kc += 32) {
#pragma unroll
        for (int j = 0; j < 16; j++) {
            int idx = t + j * 256;          // 0..4095
            int n = idx >> 5, kk = idx & 31;
            Ws[kk][n] = W[n * 128 + kc + kk];
        }
#pragma unroll
        for (int j = 0; j < 8; j++) {
            int idx = t + j * 256;          // 0..2047
            int row = idx >> 5, kk = idx & 31;
            Xs[row][kk] = X[(row0 + row) * 128 + kc + kk];
        }
        __syncthreads();

#pragma unroll 8
        for (int kk = 0; kk < 32; kk++) {
            ulonglong2 w2 = *(const ulonglong2*)&Ws[kk][lane * 4];
#pragma unroll
            for (int i = 0; i < 8; i++) {
                float x = Xs[w * 8 + i][kk];   // warp-broadcast LDS
                u64 x2 = pack2(x, x);
                ffma2(acc[i][0], x2, w2.x);
                ffma2(acc[i][1], x2, w2.y);
            }
        }
        __syncthreads();
    }

#pragma unroll
    for (int i = 0; i < 8; i++) {
        ulonglong2 o; o.x = acc[i][0]; o.y = acc[i][1];
        *(ulonglong2*)&Out[(row0 + w * 8 + i) * 128 + lane * 4] = o;
    }

    // Segment boundaries (only in the Q pass, block 0): g_rseg[b] =
    // lower_bound(residue_batch, b). Ready before attn by stream ordering.
    if (outsel == 0 && blockIdx.x == 0 && t <= NB) {
        int b = t, lo = 0, hi = R_N;
        while (lo < hi) {
            int mid = (lo + hi) >> 1;
            if (rb[mid] < b) lo = mid + 1; else hi = mid;
        }
        g_rseg[b] = lo;
    }
}

// ---------------------------------------------------------------------------
// Attention: 64 atoms/block, 256 threads, 32-residue K/V tiles, online
// softmax. Warp w owns atoms w*8..w*8+7.
//   scores: lane = residue in tile;   PV/out: lane = dim quad (lane*4..+3)
// All FMA-heavy loops use packed f32x2.
// ---------------------------------------------------------------------------
__global__ __launch_bounds__(256, 2) void attn_kernel(
    const float* __restrict__ atom_h,
    const int* __restrict__ atom_batch,
    const int* __restrict__ residue_batch,
    float* __restrict__ out)
{
    extern __shared__ float sm[];
    float* Qs = sm;                     // 64*128
    float* Ks = Qs + 64 * 128;          // 32*132 (padded rows, 16B-aligned)
    float* Vs = Ks + 32 * 132;          // 32*128
    float* Ps = Vs + 32 * 128;          // 64*32
    int*   ab  = (int*)(Ps + 64 * 32);  // 64
    int*   rbs = ab + 64;               // 32

    int t = threadIdx.x;
    int lane = t & 31;
    int w = t >> 5;
    int a0 = blockIdx.x * 64;

    {
        const float4* src = (const float4*)(g_Q + a0 * 128);
        float4* dst = (float4*)Qs;
#pragma unroll
        for (int j = 0; j < 8; j++) dst[t + j * 256] = src[t + j * 256];
    }
    if (t < 64) ab[t] = atom_batch[a0 + t];
    __syncthreads();

    // Sorted batches => the block's residue union is one contiguous interval.
    int r0 = g_rseg[ab[0]];
    int r1 = g_rseg[ab[63] + 1];

    u64 acc[8][2];
    float mcur[8], lsum[8];
    int myb[8];
#pragma unroll
    for (int i = 0; i < 8; i++) {
        acc[i][0] = 0ull; acc[i][1] = 0ull;
        mcur[i] = -1e30f;
        lsum[i] = 0.f;
        myb[i] = ab[w * 8 + i];
    }
    const float inv_scale = 0.08838834764831845f;  // 1/sqrt(128)
    int d0 = lane * 4;

    for (int rt = r0; rt < r1; rt += 32) {
        int nr = r1 - rt; if (nr > 32) nr = 32;

        // Stage K (stride 132) and V (stride 128); zero-fill tail.
#pragma unroll
        for (int j = 0; j < 4; j++) {
            int idx = t + j * 256;          // 0..1023 float4 slots
            int r = idx >> 5, c4 = idx & 31;
            float4 kv, vv;
            if (r < nr) {
                kv = ((const float4*)(g_K + (rt + r) * 128))[c4];
                vv = ((const float4*)(g_V + (rt + r) * 128))[c4];
            } else {
                kv = make_float4(0.f, 0.f, 0.f, 0.f);
                vv = kv;
            }
            *(float4*)&Ks[r * 132 + c4 * 4] = kv;
            *(float4*)&Vs[r * 128 + c4 * 4] = vv;
        }
        if (t < 32) rbs[t] = (t < nr) ? residue_batch[rt + t] : -1;
        __syncthreads();

        // Scores: s[i] = Q[a_i] . K[lane], packed-pair accumulation.
        u64 s2[8];
#pragma unroll
        for (int i = 0; i < 8; i++) s2[i] = 0ull;
#pragma unroll 8
        for (int k0 = 0; k0 < 128; k0 += 4) {
            ulonglong2 k2 = *(const ulonglong2*)&Ks[lane * 132 + k0];
#pragma unroll
            for (int i = 0; i < 8; i++) {
                ulonglong2 q2 = *(const ulonglong2*)&Qs[(w * 8 + i) * 128 + k0];
                ffma2(s2[i], q2.x, k2.x);
                ffma2(s2[i], q2.y, k2.y);
            }
        }

        // Online softmax; one warp owns all 32 residue scores of a row.
        int rbv = rbs[lane];
#pragma unroll
        for (int i = 0; i < 8; i++) {
            float slo, shi; unpack2(slo, shi, s2[i]);
            float s = slo + shi;
            float sv = (myb[i] == rbv) ? s * inv_scale : -1e30f;
            float tm = sv;
#pragma unroll
            for (int o = 16; o > 0; o >>= 1)
                tm = fmaxf(tm, __shfl_xor_sync(0xffffffffu, tm, o));
            float mnew = fmaxf(mcur[i], tm);
            float p = (sv > -1e29f) ? __expf(sv - mnew) : 0.f;
            float ps = p;
#pragma unroll
            for (int o = 16; o > 0; o >>= 1)
                ps += __shfl_xor_sync(0xffffffffu, ps, o);
            float factor = __expf(mcur[i] - mnew);   // =1 while row empty
            lsum[i] = lsum[i] * factor + ps;
            mcur[i] = mnew;
            u64 f2 = pack2(factor, factor);
            fmul2(acc[i][0], acc[i][0], f2);
            fmul2(acc[i][1], acc[i][1], f2);
            Ps[(w * 8 + i) * 32 + lane] = p;
        }
        __syncwarp();   // producer == consumer warp for Ps rows

        // PV accumulate: lane owns dims d0..d0+3.
#pragma unroll 8
        for (int r = 0; r < 32; r++) {
            ulonglong2 v2 = *(const ulonglong2*)&Vs[r * 128 + d0];
#pragma unroll
            for (int i = 0; i < 8; i++) {
                float p = Ps[(w * 8 + i) * 32 + r];   // broadcast LDS
                u64 p2 = pack2(p, p);
                ffma2(acc[i][0], p2, v2.x);
                ffma2(acc[i][1], p2, v2.y);
            }
        }
        __syncthreads();
    }

    // Epilogue: out = atom_h + ctx (unchanged if graph had no residues).
#pragma unroll
    for (int i = 0; i < 8; i++) {
        int a = a0 + w * 8 + i;
        float4 h = ((const float4*)(atom_h + a * 128))[lane];
        float invl = (lsum[i] > 0.f) ? 1.f / lsum[i] : 0.f;
        float c0, c1, c2, c3;
        unpack2(c0, c1, acc[i][0]);
        unpack2(c2, c3, acc[i][1]);
        float4 o;
        o.x = h.x + c0 * invl;
        o.y = h.y + c1 * invl;
        o.z = h.z + c2 * invl;
        o.w = h.w + c3 * invl;
        ((float4*)(out + a * 128))[lane] = o;
    }
}

// ---------------------------------------------------------------------------
extern "C" void kernel_launch(void* const* d_in, const int* in_sizes, int n_in,
                              void* d_out, int out_size)
{
    const float* atom_h        = (const float*)d_in[0];
    const float* residue_h     = (const float*)d_in[1];
    const int*   atom_batch    = (const int*)d_in[2];
    const int*   residue_batch = (const int*)d_in[3];
    const float* W_q           = (const float*)d_in[4];
    const float* W_k           = (const float*)d_in[5];
    const float* W_v           = (const float*)d_in[6];
    float* out = (float*)d_out;

    gemm_nt_kernel<<<A_N / 64, 256>>>(atom_h, W_q, 0, residue_batch);     // Q + rseg
    gemm_nt_kernel<<<R_N / 64, 256>>>(residue_h, W_k, 1, residue_batch);  // K
    gemm_nt_kernel<<<R_N / 64, 256>>>(residue_h, W_v, 2, residue_batch);  // V

    const int SMEM = (64 * 128 + 32 * 132 + 32 * 128 + 64 * 32) * 4 + (64 + 32) * 4;
    cudaFuncSetAttribute(attn_kernel,
                         cudaFuncAttributeMaxDynamicSharedMemorySize, SMEM);
    attn_kernel<<<A_N / 64, 256, SMEM>>>(atom_h, atom_batch, residue_batch, out);
}